// round 7
// baseline (speedup 1.0000x reference)
#include <cuda_runtime.h>
#include <cstdint>

#define B_ 2
#define S_ 1024
#define D_ 128

typedef unsigned long long u64;

// ---------------- scratch ----------------
__device__ float g_Qt[B_*D_*S_];     // q' = 1-Q, transposed [b][d][s]
__device__ float g_Kt[B_*D_*S_];     // k' = 1-K, transposed [b][d][s]
__device__ float g_sumK[B_*S_];      // 128 - sum_d k' per row
__device__ float g_V[B_*S_*D_];      // V [b][s][d]
__device__ float g_Z[B_*S_];         // row sums of E' = exp(10T)-1
__device__ float g_totVp[128*128];   // per-qkv-block partial sums of V
__device__ unsigned g_ctr;           // monotone barrier counter (never reset)

__device__ __forceinline__ u64 pack2(float a, float b){
  u64 r; asm("mov.b64 %0, {%1, %2};" : "=l"(r) : "f"(a), "f"(b)); return r;
}
__device__ __forceinline__ void unpack2(u64 v, float& a, float& b){
  asm("mov.b64 {%0, %1}, %2;" : "=f"(a), "=f"(b) : "l"(v));
}
__device__ __forceinline__ u64 fma2(u64 a, u64 b, u64 c){
  u64 d; asm("fma.rn.f32x2 %0, %1, %2, %3;" : "=l"(d) : "l"(a), "l"(b), "l"(c)); return d;
}

// ---------------- K1: QKV (+ zero out/Z + zero att upper + totV partials)
// 128 blocks x 512 threads, 16 seq rows per block.
__global__ void __launch_bounds__(512) k_qkv(
    const float* __restrict__ x,
    const float* __restrict__ wq, const float* __restrict__ bq,
    const float* __restrict__ wk, const float* __restrict__ bk,
    const float* __restrict__ wv, const float* __restrict__ bv,
    float* __restrict__ outp){
  extern __shared__ float sm[];
  float* ws = sm;                 // [2][3][32][128]  = 24576 floats
  float* xs = sm + 24576;         // [16][128]        = 2048 floats
  __shared__ float wred[16][4];
  __shared__ float wtot[4][128];

  int t = threadIdx.x;
  int o = t & 127;                // output dim
  int h = t >> 7;                 // row group (4 rows each), 0..3
  int s0 = blockIdx.x*16;
  int b  = s0 >> 10;
  int sl = s0 & 1023;

  // zero the out region (65536 f4 over 128 blocks) + g_Z
  ((float4*)outp)[blockIdx.x*512 + t] = make_float4(0.f,0.f,0.f,0.f);
  if (t < 16) g_Z[blockIdx.x*16 + t] = 0.f;

  // zero att cols not covered by any compute tile: [q0u+128, 1024)
  {
    float* att = outp + B_*S_*D_;
    int q0u = sl & ~127;
    int start = q0u + 128;
    if (start < 1024){
      int w4 = (1024 - start) >> 2;      // <= 224
      float4 z4 = make_float4(0.f,0.f,0.f,0.f);
      #pragma unroll
      for (int row=0; row<16; row++){
        if (t < w4)
          ((float4*)(att + (b*S_ + sl + row)*S_ + start))[t] = z4;
      }
    }
  }

  // stage x tile [16 s][128 d] row-major
  ((float4*)xs)[t] = ((const float4*)(x + s0*D_))[t];

  const float4* wq4 = (const float4*)wq;
  const float4* wk4 = (const float4*)wk;
  const float4* wv4 = (const float4*)wv;
  float4* ws4 = (float4*)ws;

  // stage chunk 0 into buffer 0
  #pragma unroll
  for (int j=0;j<6;j++){
    int i = t + j*512;
    int m = i >> 10, r = i & 1023;
    const float4* src = (m==0)? wq4 : (m==1)? wk4 : wv4;
    ws4[i] = src[((r>>5))*32 + (r&31)];
  }
  __syncthreads();

  u64 aq[4], ak[4], av[4];
  #pragma unroll
  for (int jr=0;jr<4;jr++){ aq[jr]=0ull; ak[jr]=0ull; av[jr]=0ull; }

  #pragma unroll 1
  for (int c=0; c<4; c++){
    if (c < 3){
      int f = (c+1)&1;
      #pragma unroll
      for (int j=0;j<6;j++){
        int i = t + j*512;
        int m = i >> 10, r = i & 1023;
        const float4* src = (m==0)? wq4 : (m==1)? wk4 : wv4;
        ws4[f*3072 + i] = src[((c+1)*32 + (r>>5))*32 + (r&31)];
      }
    }
    const float* wb = ws + (c&1)*12288;
    #pragma unroll 4
    for (int dp=0; dp<16; dp++){
      int d0 = dp*2;
      u64 xp0 = *(const u64*)&xs[(h*4+0)*128 + c*32 + d0];
      u64 xp1 = *(const u64*)&xs[(h*4+1)*128 + c*32 + d0];
      u64 xp2 = *(const u64*)&xs[(h*4+2)*128 + c*32 + d0];
      u64 xp3 = *(const u64*)&xs[(h*4+3)*128 + c*32 + d0];
      u64 wqp = pack2(wb[          d0*128 + o], wb[          (d0+1)*128 + o]);
      u64 wkp = pack2(wb[ 4096 +   d0*128 + o], wb[ 4096 +   (d0+1)*128 + o]);
      u64 wvp = pack2(wb[ 8192 +   d0*128 + o], wb[ 8192 +   (d0+1)*128 + o]);
      aq[0]=fma2(wqp,xp0,aq[0]); aq[1]=fma2(wqp,xp1,aq[1]);
      aq[2]=fma2(wqp,xp2,aq[2]); aq[3]=fma2(wqp,xp3,aq[3]);
      ak[0]=fma2(wkp,xp0,ak[0]); ak[1]=fma2(wkp,xp1,ak[1]);
      ak[2]=fma2(wkp,xp2,ak[2]); ak[3]=fma2(wkp,xp3,ak[3]);
      av[0]=fma2(wvp,xp0,av[0]); av[1]=fma2(wvp,xp1,av[1]);
      av[2]=fma2(wvp,xp2,av[2]); av[3]=fma2(wvp,xp3,av[3]);
    }
    __syncthreads();
  }

  float bqv = bq[o], bkv = bk[o], bvv = bv[o];
  float qv[4], kv[4], vv[4];
  #pragma unroll
  for (int jr=0;jr<4;jr++){
    float a0,a1;
    unpack2(aq[jr],a0,a1); qv[jr] = a0+a1+bqv;
    unpack2(ak[jr],a0,a1); kv[jr] = a0+a1+bkv;
    unpack2(av[jr],a0,a1); vv[jr] = a0+a1+bvv;
  }
  // primes: q' = 1 - sigmoid(z) = 1/(1+exp(z))
  #pragma unroll
  for (int jr=0;jr<4;jr++){
    qv[jr] = 1.f/(1.f+__expf(qv[jr]));
    kv[jr] = 1.f/(1.f+__expf(kv[jr]));
  }

  #pragma unroll
  for (int jr=0;jr<4;jr++) g_V[(s0 + h*4 + jr)*D_ + o] = vv[jr];

  ((float4*)(g_Qt + b*D_*S_ + o*S_ + sl + h*4))[0] =
      make_float4(qv[0],qv[1],qv[2],qv[3]);
  ((float4*)(g_Kt + b*D_*S_ + o*S_ + sl + h*4))[0] =
      make_float4(kv[0],kv[1],kv[2],kv[3]);

  // totV partial for this block: sum of its 16 V rows, per o
  wtot[h][o] = vv[0]+vv[1]+vv[2]+vv[3];

  // sumK = 128 - sum_d k'
  float red[4] = {kv[0],kv[1],kv[2],kv[3]};
  #pragma unroll
  for (int off=16; off>=1; off>>=1){
    #pragma unroll
    for (int jr=0;jr<4;jr++) red[jr] += __shfl_xor_sync(0xffffffffu, red[jr], off);
  }
  int w = t >> 5;
  if ((t & 31) == 0){
    #pragma unroll
    for (int jr=0;jr<4;jr++) wred[w][jr] = red[jr];
  }
  __syncthreads();
  if (t < 16){
    int r = t, hh = r >> 2, jr = r & 3;
    float tot = wred[hh*4+0][jr]+wred[hh*4+1][jr]+wred[hh*4+2][jr]+wred[hh*4+3][jr];
    g_sumK[s0 + r] = 128.f - tot;
  }
  if (t < 128)
    g_totVp[blockIdx.x*128 + t] = wtot[0][t]+wtot[1][t]+wtot[2][t]+wtot[3][t];
}

// ---------------- K2: fused truth + E' + Z + E'@V + barrier + norm -------
// 144 blocks, 1/SM (smem-padded): lower-triangle 128q x 64k tiles.
__global__ void __launch_bounds__(512) k_main(float* __restrict__ outp){
  extern __shared__ float sm[];
  float* Qts = sm;                 // [128 d][128 q] 16384 fl -> reused as Vs
  float* Kts = sm + 16384;         // [128 d][64 k]   8192 fl -> reused as Es
  float* sKs = sm + 24576;         // [64]
  float* Es  = sm + 16384;         // [64 k][pitch 132] 8448 fl (overlaps Kts+sKs)
  float* Vs  = sm;                 // [64 k][128 d]     8192 fl
  int bid = blockIdx.x;
  int t = threadIdx.x;
  float* att = outp + B_*S_*D_;

  int b = bid/72, r = bid - b*72;
  int qt = 0;
  while ((qt+1)*(qt+2) <= r) qt++;
  int k0 = (r - qt*(qt+1))*64;
  int q0 = qt*128;
  int tx = t & 15, ty = t >> 4;    // ty 0..31

  const float4* Qg = (const float4*)(g_Qt + b*D_*S_);
  const float4* Kg = (const float4*)(g_Kt + b*D_*S_);
  const float4* Vg = (const float4*)(g_V + b*S_*D_);

  float4* Qts4 = (float4*)Qts;
  float4* Kts4 = (float4*)Kts;

  // stage ALL of Q (8 f4/thr) + K (4 f4/thr) + sKs in one burst, one sync
  #pragma unroll
  for (int it=0; it<8; it++){
    int i = t + it*512;                     // 4096 f4
    Qts4[i] = Qg[(i>>5)*256 + (q0>>2) + (i&31)];
  }
  #pragma unroll
  for (int it=0; it<4; it++){
    int i = t + it*512;                     // 2048 f4
    Kts4[i] = Kg[(i>>4)*256 + (k0>>2) + (i&15)];
  }
  if (t < 64) sKs[t] = g_sumK[b*S_ + k0 + t];
  __syncthreads();

  // phase 1: acc = sum_d [k' <= q'] * k'
  float acc[4][4];
  #pragma unroll
  for (int i=0;i<4;i++)
    #pragma unroll
    for (int j=0;j<4;j++) acc[i][j] = 0.f;

  #pragma unroll 4
  for (int d=0; d<128; d++){
    float4 qa = Qts4[d*32 + ty];
    float4 kf = Kts4[d*16 + tx];
    float qq[4] = {qa.x,qa.y,qa.z,qa.w};
    float kk[4] = {kf.x,kf.y,kf.z,kf.w};
    #pragma unroll
    for (int i=0;i<4;i++){
      #pragma unroll
      for (int j=0;j<4;j++){
        asm("{.reg .f32 m; set.le.f32.f32 m, %1, %2; fma.rn.f32 %0, m, %1, %0;}"
            : "+f"(acc[i][j]) : "f"(kk[j]), "f"(qq[i]));
      }
    }
  }

  // phase 2: T, att store, E' = exp(10T)-1, Z partial
  const float inv = 1.f/128.f;
  float e[4][4];
  #pragma unroll
  for (int i=0;i<4;i++){
    int qg = q0 + ty*4 + i;
    float zrow = 0.f;
    float tt[4];
    #pragma unroll
    for (int j=0;j<4;j++){
      int kg = k0 + tx*4 + j;
      float T = (acc[i][j] + sKs[tx*4+j]) * inv;
      bool val = (kg <= qg);
      T = val ? T : 0.f;
      float ee = val ? (__expf(10.f*T) - 1.f) : 0.f;
      tt[j] = T; e[i][j] = ee; zrow += ee;
    }
    ((float4*)(att + (b*S_ + qg)*S_ + k0 + tx*4))[0] =
        make_float4(tt[0],tt[1],tt[2],tt[3]);
    #pragma unroll
    for (int off=8; off>=1; off>>=1)
      zrow += __shfl_xor_sync(0xffffffffu, zrow, off);
    if (tx == 0) atomicAdd(&g_Z[b*S_ + qg], zrow);
  }
  __syncthreads();     // all reads of Qts/Kts/sKs done

  // phase 3: stage E' (pitch 132, f4-aligned) + V tile
  #pragma unroll
  for (int j=0;j<4;j++){
    int kl = tx*4 + j;
    ((float4*)&Es[kl*132 + ty*4])[0] =
        make_float4(e[0][j], e[1][j], e[2][j], e[3][j]);
  }
  float4* Vs4 = (float4*)Vs;
  #pragma unroll
  for (int it=0; it<4; it++){
    int i = t + it*512;                     // 2048 f4
    Vs4[i] = Vg[(k0 + (i>>5))*32 + (i&31)];
  }
  __syncthreads();

  // phase 4: out += E'^T @ V   (4q x 8d per thread, f32x2)
  u64 acc2[4][4];
  #pragma unroll
  for (int i=0;i<4;i++)
    #pragma unroll
    for (int j=0;j<4;j++) acc2[i][j] = 0ull;

  #pragma unroll 2
  for (int k=0;k<64;k++){
    float4 ef = *(const float4*)&Es[k*132 + ty*4];
    const u64* vr = (const u64*)&Vs[k*128 + tx*8];
    u64 v0 = vr[0], v1 = vr[1], v2 = vr[2], v3 = vr[3];
    float ev[4] = {ef.x,ef.y,ef.z,ef.w};
    #pragma unroll
    for (int i=0;i<4;i++){
      u64 e2 = pack2(ev[i], ev[i]);
      acc2[i][0] = fma2(e2, v0, acc2[i][0]);
      acc2[i][1] = fma2(e2, v1, acc2[i][1]);
      acc2[i][2] = fma2(e2, v2, acc2[i][2]);
      acc2[i][3] = fma2(e2, v3, acc2[i][3]);
    }
  }

  #pragma unroll
  for (int i=0;i<4;i++){
    int qg = q0 + ty*4 + i;
    float* op = outp + (b*S_ + qg)*D_ + tx*8;
    float a0,a1,a2,a3,a4,a5,a6,a7;
    unpack2(acc2[i][0],a0,a1);
    unpack2(acc2[i][1],a2,a3);
    unpack2(acc2[i][2],a4,a5);
    unpack2(acc2[i][3],a6,a7);
    atomicAdd((float4*)op,       make_float4(a0,a1,a2,a3));
    atomicAdd((float4*)(op + 4), make_float4(a4,a5,a6,a7));
  }

  // ---- monotone cohort barrier (144 blocks, all resident at 1/SM) ----
  __threadfence();
  __syncthreads();
  if (t == 0){
    unsigned old = atomicAdd(&g_ctr, 1u);
    unsigned target = old - (old % 144u) + 144u;
    while (atomicAdd(&g_ctr, 0u) < target) {}
  }
  __syncthreads();
  __threadfence();

  // ---- distributed normalize: out = (out + totV) / (Z + 1024) ----
  {
    int start = (bid*128)/9;               // 2048 rows over 144 blocks
    int end   = ((bid+1)*128)/9;
    int rr = t >> 5, col = t & 31;
    int row = start + rr;
    if (row < end){
      int rb = row >> 10;                  // batch of this row
      // totV[rb][col f4] = sum of 64 qkv-block partials
      const float4* tp = (const float4*)g_totVp;
      float4 tv = make_float4(0.f,0.f,0.f,0.f);
      #pragma unroll 8
      for (int j=0;j<64;j++){
        float4 p = tp[(rb*64 + j)*32 + col];
        tv.x += p.x; tv.y += p.y; tv.z += p.z; tv.w += p.w;
      }
      float4* o4 = (float4*)outp;
      float4 v = o4[row*32 + col];
      float rz = 1.f/(g_Z[row] + 1024.f);
      v.x=(v.x+tv.x)*rz; v.y=(v.y+tv.y)*rz;
      v.z=(v.z+tv.z)*rz; v.w=(v.w+tv.w)*rz;
      o4[row*32 + col] = v;
    }
  }
}

// ---------------- launch ----------------
extern "C" void kernel_launch(void* const* d_in, const int* in_sizes, int n_in,
                              void* d_out, int out_size){
  (void)in_sizes; (void)n_in; (void)out_size;
  const float* x  = (const float*)d_in[0];
  const float* wq = (const float*)d_in[1];
  const float* bq = (const float*)d_in[2];
  const float* wk = (const float*)d_in[3];
  const float* bk = (const float*)d_in[4];
  const float* wv = (const float*)d_in[5];
  const float* bv = (const float*)d_in[6];
  float* out = (float*)d_out;              // (output, attention_truth)

  const int SMQ = (24576 + 2048) * 4;      // 106,496 B
  const int SMM = 120000;                  // pad: forces 1 block/SM (>113KB)
  cudaFuncSetAttribute(k_qkv,  cudaFuncAttributeMaxDynamicSharedMemorySize, SMQ);
  cudaFuncSetAttribute(k_main, cudaFuncAttributeMaxDynamicSharedMemorySize, SMM);

  k_qkv  <<< 128, 512, SMQ >>>(x, wq, bq, wk, bk, wv, bv, out);
  k_main <<< 144, 512, SMM >>>(out);
}

// round 9
// speedup vs baseline: 1.0269x; 1.0269x over previous
#include <cuda_runtime.h>
#include <cstdint>

#define B_ 2
#define S_ 1024
#define D_ 128

typedef unsigned long long u64;

// ---------------- scratch ----------------
__device__ float g_Qt[B_*D_*S_];     // q' = 1-Q, transposed [b][d][s]
__device__ float g_Kt[B_*D_*S_];     // k' = 1-K, transposed [b][d][s]
__device__ float g_sumK[B_*S_];      // 128 - sum_d k' per row
__device__ float g_V[B_*S_*D_];      // V [b][s][d]
__device__ float g_Z[B_*S_];         // row sums of E' = exp(10T)-1
__device__ float g_totVp[128*128];   // per-qkv-block partial sums of V

__device__ __forceinline__ u64 pack2(float a, float b){
  u64 r; asm("mov.b64 %0, {%1, %2};" : "=l"(r) : "f"(a), "f"(b)); return r;
}
__device__ __forceinline__ void unpack2(u64 v, float& a, float& b){
  asm("mov.b64 {%0, %1}, %2;" : "=f"(a), "=f"(b) : "l"(v));
}
__device__ __forceinline__ u64 fma2(u64 a, u64 b, u64 c){
  u64 d; asm("fma.rn.f32x2 %0, %1, %2, %3;" : "=l"(d) : "l"(a), "l"(b), "l"(c)); return d;
}

// ---------------- K1: QKV (+ zero out/Z + zero att upper + totV partials)
// 128 blocks x 512 threads, 16 seq rows per block.
__global__ void __launch_bounds__(512) k_qkv(
    const float* __restrict__ x,
    const float* __restrict__ wq, const float* __restrict__ bq,
    const float* __restrict__ wk, const float* __restrict__ bk,
    const float* __restrict__ wv, const float* __restrict__ bv,
    float* __restrict__ outp){
  extern __shared__ float sm[];
  float* ws = sm;                 // [2][3][32][128]  = 24576 floats
  float* xs = sm + 24576;         // [16][128]        = 2048 floats
  __shared__ float wred[16][4];
  __shared__ float wtot[4][128];

  int t = threadIdx.x;
  int o = t & 127;                // output dim
  int h = t >> 7;                 // row group (4 rows each), 0..3
  int s0 = blockIdx.x*16;
  int b  = s0 >> 10;
  int sl = s0 & 1023;

  // zero the out region (65536 f4 over 128 blocks) + g_Z
  ((float4*)outp)[blockIdx.x*512 + t] = make_float4(0.f,0.f,0.f,0.f);
  if (t < 16) g_Z[blockIdx.x*16 + t] = 0.f;

  // zero att cols not covered by any compute tile: [q0u+128, 1024)
  {
    float* att = outp + B_*S_*D_;
    int q0u = sl & ~127;
    int start = q0u + 128;
    if (start < 1024){
      int w4 = (1024 - start) >> 2;      // <= 224
      float4 z4 = make_float4(0.f,0.f,0.f,0.f);
      #pragma unroll
      for (int row=0; row<16; row++){
        if (t < w4)
          ((float4*)(att + (b*S_ + sl + row)*S_ + start))[t] = z4;
      }
    }
  }

  // stage x tile [16 s][128 d] row-major
  ((float4*)xs)[t] = ((const float4*)(x + s0*D_))[t];

  const float4* wq4 = (const float4*)wq;
  const float4* wk4 = (const float4*)wk;
  const float4* wv4 = (const float4*)wv;
  float4* ws4 = (float4*)ws;

  // stage chunk 0 into buffer 0
  #pragma unroll
  for (int j=0;j<6;j++){
    int i = t + j*512;
    int m = i >> 10, r = i & 1023;
    const float4* src = (m==0)? wq4 : (m==1)? wk4 : wv4;
    ws4[i] = src[((r>>5))*32 + (r&31)];
  }
  __syncthreads();

  u64 aq[4], ak[4], av[4];
  #pragma unroll
  for (int jr=0;jr<4;jr++){ aq[jr]=0ull; ak[jr]=0ull; av[jr]=0ull; }

  #pragma unroll 1
  for (int c=0; c<4; c++){
    if (c < 3){
      int f = (c+1)&1;
      #pragma unroll
      for (int j=0;j<6;j++){
        int i = t + j*512;
        int m = i >> 10, r = i & 1023;
        const float4* src = (m==0)? wq4 : (m==1)? wk4 : wv4;
        ws4[f*3072 + i] = src[((c+1)*32 + (r>>5))*32 + (r&31)];
      }
    }
    const float* wb = ws + (c&1)*12288;
    #pragma unroll 4
    for (int dp=0; dp<16; dp++){
      int d0 = dp*2;
      u64 xp0 = *(const u64*)&xs[(h*4+0)*128 + c*32 + d0];
      u64 xp1 = *(const u64*)&xs[(h*4+1)*128 + c*32 + d0];
      u64 xp2 = *(const u64*)&xs[(h*4+2)*128 + c*32 + d0];
      u64 xp3 = *(const u64*)&xs[(h*4+3)*128 + c*32 + d0];
      u64 wqp = pack2(wb[          d0*128 + o], wb[          (d0+1)*128 + o]);
      u64 wkp = pack2(wb[ 4096 +   d0*128 + o], wb[ 4096 +   (d0+1)*128 + o]);
      u64 wvp = pack2(wb[ 8192 +   d0*128 + o], wb[ 8192 +   (d0+1)*128 + o]);
      aq[0]=fma2(wqp,xp0,aq[0]); aq[1]=fma2(wqp,xp1,aq[1]);
      aq[2]=fma2(wqp,xp2,aq[2]); aq[3]=fma2(wqp,xp3,aq[3]);
      ak[0]=fma2(wkp,xp0,ak[0]); ak[1]=fma2(wkp,xp1,ak[1]);
      ak[2]=fma2(wkp,xp2,ak[2]); ak[3]=fma2(wkp,xp3,ak[3]);
      av[0]=fma2(wvp,xp0,av[0]); av[1]=fma2(wvp,xp1,av[1]);
      av[2]=fma2(wvp,xp2,av[2]); av[3]=fma2(wvp,xp3,av[3]);
    }
    __syncthreads();
  }

  float bqv = bq[o], bkv = bk[o], bvv = bv[o];
  float qv[4], kv[4], vv[4];
  #pragma unroll
  for (int jr=0;jr<4;jr++){
    float a0,a1;
    unpack2(aq[jr],a0,a1); qv[jr] = a0+a1+bqv;
    unpack2(ak[jr],a0,a1); kv[jr] = a0+a1+bkv;
    unpack2(av[jr],a0,a1); vv[jr] = a0+a1+bvv;
  }
  // primes: q' = 1 - sigmoid(z) = 1/(1+exp(z))
  #pragma unroll
  for (int jr=0;jr<4;jr++){
    qv[jr] = 1.f/(1.f+__expf(qv[jr]));
    kv[jr] = 1.f/(1.f+__expf(kv[jr]));
  }

  #pragma unroll
  for (int jr=0;jr<4;jr++) g_V[(s0 + h*4 + jr)*D_ + o] = vv[jr];

  ((float4*)(g_Qt + b*D_*S_ + o*S_ + sl + h*4))[0] =
      make_float4(qv[0],qv[1],qv[2],qv[3]);
  ((float4*)(g_Kt + b*D_*S_ + o*S_ + sl + h*4))[0] =
      make_float4(kv[0],kv[1],kv[2],kv[3]);

  // totV partial for this block
  wtot[h][o] = vv[0]+vv[1]+vv[2]+vv[3];

  // sumK = 128 - sum_d k'
  float red[4] = {kv[0],kv[1],kv[2],kv[3]};
  #pragma unroll
  for (int off=16; off>=1; off>>=1){
    #pragma unroll
    for (int jr=0;jr<4;jr++) red[jr] += __shfl_xor_sync(0xffffffffu, red[jr], off);
  }
  int w = t >> 5;
  if ((t & 31) == 0){
    #pragma unroll
    for (int jr=0;jr<4;jr++) wred[w][jr] = red[jr];
  }
  __syncthreads();
  if (t < 16){
    int r = t, hh = r >> 2, jr = r & 3;
    float tot = wred[hh*4+0][jr]+wred[hh*4+1][jr]+wred[hh*4+2][jr]+wred[hh*4+3][jr];
    g_sumK[s0 + r] = 128.f - tot;
  }
  if (t < 128)
    g_totVp[blockIdx.x*128 + t] = wtot[0][t]+wtot[1][t]+wtot[2][t]+wtot[3][t];
}

// ---------------- K2: fused truth + E' + Z + E'@V ------------------------
// 144 blocks (one wave, 1/SM): lower-triangle 128q x 64k tiles.
__global__ void __launch_bounds__(512,1) k_main(float* __restrict__ outp){
  extern __shared__ float sm[];
  float* Qts = sm;                 // [128 d][128 q] 16384 fl -> reused as Vs
  float* Kts = sm + 16384;         // [128 d][64 k]   8192 fl -> reused as Es
  float* sKs = sm + 24576;         // [64]
  float* Es  = sm + 16384;         // [64 k][pitch 132] 8448 fl
  float* Vs  = sm;                 // [64 k][128 d]     8192 fl
  int bid = blockIdx.x;
  int t = threadIdx.x;
  float* att = outp + B_*S_*D_;

  int b = bid/72, r = bid - b*72;
  int qt = 0;
  while ((qt+1)*(qt+2) <= r) qt++;
  int k0 = (r - qt*(qt+1))*64;
  int q0 = qt*128;
  int tx = t & 15, ty = t >> 4;    // ty 0..31

  const float4* Qg = (const float4*)(g_Qt + b*D_*S_);
  const float4* Kg = (const float4*)(g_Kt + b*D_*S_);
  const float4* Vg = (const float4*)(g_V + b*S_*D_);

  float4* Qts4 = (float4*)Qts;
  float4* Kts4 = (float4*)Kts;

  // stage Q (8 f4/thr) + K (4 f4/thr) + sKs, one sync
  #pragma unroll
  for (int it=0; it<8; it++){
    int i = t + it*512;                     // 4096 f4
    Qts4[i] = Qg[(i>>5)*256 + (q0>>2) + (i&31)];
  }
  #pragma unroll
  for (int it=0; it<4; it++){
    int i = t + it*512;                     // 2048 f4
    Kts4[i] = Kg[(i>>4)*256 + (k0>>2) + (i&15)];
  }
  if (t < 64) sKs[t] = g_sumK[b*S_ + k0 + t];
  __syncthreads();

  // phase 1: acc = sum_d [k' <= q'] * k'
  float acc[4][4];
  #pragma unroll
  for (int i=0;i<4;i++)
    #pragma unroll
    for (int j=0;j<4;j++) acc[i][j] = 0.f;

  #pragma unroll 4
  for (int d=0; d<128; d++){
    float4 qa = Qts4[d*32 + ty];
    float4 kf = Kts4[d*16 + tx];
    float qq[4] = {qa.x,qa.y,qa.z,qa.w};
    float kk[4] = {kf.x,kf.y,kf.z,kf.w};
    #pragma unroll
    for (int i=0;i<4;i++){
      #pragma unroll
      for (int j=0;j<4;j++){
        asm("{.reg .f32 m; set.le.f32.f32 m, %1, %2; fma.rn.f32 %0, m, %1, %0;}"
            : "+f"(acc[i][j]) : "f"(kk[j]), "f"(qq[i]));
      }
    }
  }

  // phase 2: T, att store, E' = exp(10T)-1, Z partial
  const float inv = 1.f/128.f;
  float e[4][4];
  #pragma unroll
  for (int i=0;i<4;i++){
    int qg = q0 + ty*4 + i;
    float zrow = 0.f;
    float tt[4];
    #pragma unroll
    for (int j=0;j<4;j++){
      int kg = k0 + tx*4 + j;
      float T = (acc[i][j] + sKs[tx*4+j]) * inv;
      bool val = (kg <= qg);
      T = val ? T : 0.f;
      float ee = val ? (__expf(10.f*T) - 1.f) : 0.f;
      tt[j] = T; e[i][j] = ee; zrow += ee;
    }
    ((float4*)(att + (b*S_ + qg)*S_ + k0 + tx*4))[0] =
        make_float4(tt[0],tt[1],tt[2],tt[3]);
    #pragma unroll
    for (int off=8; off>=1; off>>=1)
      zrow += __shfl_xor_sync(0xffffffffu, zrow, off);
    if (tx == 0) atomicAdd(&g_Z[b*S_ + qg], zrow);
  }
  __syncthreads();     // all reads of Qts/Kts/sKs done

  // phase 3: stage E' (pitch 132, f4-aligned) + V tile
  #pragma unroll
  for (int j=0;j<4;j++){
    int kl = tx*4 + j;
    ((float4*)&Es[kl*132 + ty*4])[0] =
        make_float4(e[0][j], e[1][j], e[2][j], e[3][j]);
  }
  float4* Vs4 = (float4*)Vs;
  #pragma unroll
  for (int it=0; it<4; it++){
    int i = t + it*512;                     // 2048 f4
    Vs4[i] = Vg[(k0 + (i>>5))*32 + (i&31)];
  }
  __syncthreads();

  // phase 4: out += E'^T @ V   (4q x 8d per thread, f32x2)
  u64 acc2[4][4];
  #pragma unroll
  for (int i=0;i<4;i++)
    #pragma unroll
    for (int j=0;j<4;j++) acc2[i][j] = 0ull;

  #pragma unroll 2
  for (int k=0;k<64;k++){
    float4 ef = *(const float4*)&Es[k*132 + ty*4];
    const u64* vr = (const u64*)&Vs[k*128 + tx*8];
    u64 v0 = vr[0], v1 = vr[1], v2 = vr[2], v3 = vr[3];
    float ev[4] = {ef.x,ef.y,ef.z,ef.w};
    #pragma unroll
    for (int i=0;i<4;i++){
      u64 e2 = pack2(ev[i], ev[i]);
      acc2[i][0] = fma2(e2, v0, acc2[i][0]);
      acc2[i][1] = fma2(e2, v1, acc2[i][1]);
      acc2[i][2] = fma2(e2, v2, acc2[i][2]);
      acc2[i][3] = fma2(e2, v3, acc2[i][3]);
    }
  }

  #pragma unroll
  for (int i=0;i<4;i++){
    int qg = q0 + ty*4 + i;
    float* op = outp + (b*S_ + qg)*D_ + tx*8;
    float a0,a1,a2,a3,a4,a5,a6,a7;
    unpack2(acc2[i][0],a0,a1);
    unpack2(acc2[i][1],a2,a3);
    unpack2(acc2[i][2],a4,a5);
    unpack2(acc2[i][3],a6,a7);
    atomicAdd((float4*)op,       make_float4(a0,a1,a2,a3));
    atomicAdd((float4*)(op + 4), make_float4(a4,a5,a6,a7));
  }
}

// ---------------- K3: out = (out + totV) / (Z + 1024) --------------------
// 128 blocks x 256 threads; each block: reduce totVp to smem, then 16 rows.
__global__ void __launch_bounds__(256) k_norm(float* __restrict__ outp){
  __shared__ float4 stot[64];              // [b][32 f4 cols]
  int t = threadIdx.x;
  // reduce the 64 per-qkv-block partials (per batch) into stot
  {
    int ft = t >> 2, p = t & 3;            // ft 0..63 target, p part
    int rb = ft >> 5, col = ft & 31;
    const float4* tp = (const float4*)g_totVp;
    float4 a = make_float4(0.f,0.f,0.f,0.f);
    #pragma unroll 4
    for (int j = p*16; j < p*16+16; j++){
      float4 v = tp[(rb*64 + j)*32 + col];
      a.x+=v.x; a.y+=v.y; a.z+=v.z; a.w+=v.w;
    }
    #pragma unroll
    for (int off=1; off<4; off<<=1){
      a.x += __shfl_xor_sync(0xffffffffu, a.x, off);
      a.y += __shfl_xor_sync(0xffffffffu, a.y, off);
      a.z += __shfl_xor_sync(0xffffffffu, a.z, off);
      a.w += __shfl_xor_sync(0xffffffffu, a.w, off);
    }
    if (p == 0) stot[ft] = a;
  }
  __syncthreads();

  int col = t & 31;
  float4* o4 = (float4*)outp;
  #pragma unroll
  for (int rr=0; rr<2; rr++){
    int row = blockIdx.x*16 + (t>>5) + rr*8;   // 0..2047
    float4 v = o4[row*32 + col];
    float4 tv = stot[((row >> 10) << 5) + col];
    float rz = 1.f/(g_Z[row] + 1024.f);
    v.x=(v.x+tv.x)*rz; v.y=(v.y+tv.y)*rz;
    v.z=(v.z+tv.z)*rz; v.w=(v.w+tv.w)*rz;
    o4[row*32 + col] = v;
  }
}

// ---------------- launch ----------------
extern "C" void kernel_launch(void* const* d_in, const int* in_sizes, int n_in,
                              void* d_out, int out_size){
  (void)in_sizes; (void)n_in; (void)out_size;
  const float* x  = (const float*)d_in[0];
  const float* wq = (const float*)d_in[1];
  const float* bq = (const float*)d_in[2];
  const float* wk = (const float*)d_in[3];
  const float* bk = (const float*)d_in[4];
  const float* wv = (const float*)d_in[5];
  const float* bv = (const float*)d_in[6];
  float* out = (float*)d_out;              // (output, attention_truth)

  const int SMQ = (24576 + 2048) * 4;      // 106,496 B
  const int SMM = 24832 * 4;               // 99,328 B (Es tail included)
  cudaFuncSetAttribute(k_qkv,  cudaFuncAttributeMaxDynamicSharedMemorySize, SMQ);
  cudaFuncSetAttribute(k_main, cudaFuncAttributeMaxDynamicSharedMemorySize, SMM);

  k_qkv  <<< 128, 512, SMQ >>>(x, wq, bq, wk, bk, wv, bv, out);
  k_main <<< 144, 512, SMM >>>(out);
  k_norm <<< 128, 256 >>>(out);
}

// round 10
// speedup vs baseline: 1.0329x; 1.0058x over previous
#include <cuda_runtime.h>
#include <cstdint>

#define B_ 2
#define S_ 1024
#define D_ 128

typedef unsigned long long u64;

// ---------------- scratch ----------------
__device__ float g_Qt[B_*D_*S_];     // q' = 1-Q, transposed [b][d][s]
__device__ float g_Kt[B_*D_*S_];     // k' = 1-K, transposed [b][d][s]
__device__ float g_sumK[B_*S_];      // 128 - sum_d k' per row
__device__ float g_V[B_*S_*D_];      // V [b][s][d]
__device__ float g_Z[B_*S_];         // row sums of E' = exp(10T)-1
__device__ float g_totVp[128*128];   // per-qkv-block partial sums of V

__device__ __forceinline__ u64 pack2(float a, float b){
  u64 r; asm("mov.b64 %0, {%1, %2};" : "=l"(r) : "f"(a), "f"(b)); return r;
}
__device__ __forceinline__ void unpack2(u64 v, float& a, float& b){
  asm("mov.b64 {%0, %1}, %2;" : "=f"(a), "=f"(b) : "l"(v));
}
__device__ __forceinline__ u64 fma2(u64 a, u64 b, u64 c){
  u64 d; asm("fma.rn.f32x2 %0, %1, %2, %3;" : "=l"(d) : "l"(a), "l"(b), "l"(c)); return d;
}

// phase-1 compute: 16 (FSET,FFMA) pairs
__device__ __forceinline__ void p1c(float (&acc)[4][4], const float4& qa, const float4& kf){
  float qq[4] = {qa.x,qa.y,qa.z,qa.w};
  float kk[4] = {kf.x,kf.y,kf.z,kf.w};
  #pragma unroll
  for (int i=0;i<4;i++)
    #pragma unroll
    for (int j=0;j<4;j++)
      asm("{.reg .f32 m; set.le.f32.f32 m, %1, %2; fma.rn.f32 %0, m, %1, %0;}"
          : "+f"(acc[i][j]) : "f"(kk[j]), "f"(qq[i]));
}

// phase-4 compute: 16 fma2
__device__ __forceinline__ void p4c(u64 (&acc2)[4][4], const float4& ef, const u64* v){
  float ev[4] = {ef.x,ef.y,ef.z,ef.w};
  #pragma unroll
  for (int i=0;i<4;i++){
    u64 e2 = pack2(ev[i], ev[i]);
    acc2[i][0] = fma2(e2, v[0], acc2[i][0]);
    acc2[i][1] = fma2(e2, v[1], acc2[i][1]);
    acc2[i][2] = fma2(e2, v[2], acc2[i][2]);
    acc2[i][3] = fma2(e2, v[3], acc2[i][3]);
  }
}

// k_qkv inner compute: 12 fma2 (+3 pack)
__device__ __forceinline__ void qkvc(u64 (&aq)[4], u64 (&ak)[4], u64 (&av)[4],
                                     const u64* xp, const float* wv6){
  u64 wqp = pack2(wv6[0], wv6[1]);
  u64 wkp = pack2(wv6[2], wv6[3]);
  u64 wvp = pack2(wv6[4], wv6[5]);
  #pragma unroll
  for (int r=0;r<4;r++){
    aq[r] = fma2(wqp, xp[r], aq[r]);
    ak[r] = fma2(wkp, xp[r], ak[r]);
    av[r] = fma2(wvp, xp[r], av[r]);
  }
}

// ---------------- K1: QKV (+ zero out/Z + zero att upper + totV partials)
// 128 blocks x 512 threads, 16 seq rows per block.
__global__ void __launch_bounds__(512,1) k_qkv(
    const float* __restrict__ x,
    const float* __restrict__ wq, const float* __restrict__ bq,
    const float* __restrict__ wk, const float* __restrict__ bk,
    const float* __restrict__ wv, const float* __restrict__ bv,
    float* __restrict__ outp){
  extern __shared__ float sm[];
  float* ws = sm;                 // [2][3][32][128]  = 24576 floats
  float* xs = sm + 24576;         // [16][128]        = 2048 floats
  __shared__ float wred[16][4];
  __shared__ float wtot[4][128];

  int t = threadIdx.x;
  int o = t & 127;                // output dim
  int h = t >> 7;                 // row group (4 rows each), 0..3
  int s0 = blockIdx.x*16;
  int b  = s0 >> 10;
  int sl = s0 & 1023;

  // zero the out region (65536 f4 over 128 blocks) + g_Z
  ((float4*)outp)[blockIdx.x*512 + t] = make_float4(0.f,0.f,0.f,0.f);
  if (t < 16) g_Z[blockIdx.x*16 + t] = 0.f;

  // zero att cols not covered by any compute tile: [q0u+128, 1024)
  {
    float* att = outp + B_*S_*D_;
    int q0u = sl & ~127;
    int start = q0u + 128;
    if (start < 1024){
      int w4 = (1024 - start) >> 2;      // <= 224
      float4 z4 = make_float4(0.f,0.f,0.f,0.f);
      #pragma unroll
      for (int row=0; row<16; row++){
        if (t < w4)
          ((float4*)(att + (b*S_ + sl + row)*S_ + start))[t] = z4;
      }
    }
  }

  // stage x tile [16 s][128 d] row-major
  ((float4*)xs)[t] = ((const float4*)(x + s0*D_))[t];

  const float4* wq4 = (const float4*)wq;
  const float4* wk4 = (const float4*)wk;
  const float4* wv4 = (const float4*)wv;
  float4* ws4 = (float4*)ws;

  // stage chunk 0 into buffer 0
  #pragma unroll
  for (int j=0;j<6;j++){
    int i = t + j*512;
    int m = i >> 10, r = i & 1023;
    const float4* src = (m==0)? wq4 : (m==1)? wk4 : wv4;
    ws4[i] = src[((r>>5))*32 + (r&31)];
  }
  __syncthreads();

  u64 aq[4], ak[4], av[4];
  #pragma unroll
  for (int jr=0;jr<4;jr++){ aq[jr]=0ull; ak[jr]=0ull; av[jr]=0ull; }

  #pragma unroll 1
  for (int c=0; c<4; c++){
    if (c < 3){
      int f = (c+1)&1;
      #pragma unroll
      for (int j=0;j<6;j++){
        int i = t + j*512;
        int m = i >> 10, r = i & 1023;
        const float4* src = (m==0)? wq4 : (m==1)? wk4 : wv4;
        ws4[f*3072 + i] = src[((c+1)*32 + (r>>5))*32 + (r&31)];
      }
    }
    const float* wb = ws + (c&1)*12288;
    const float* xb = xs + (h*4)*128 + c*32;

    // preload dp=0 operands
    u64 xp[4]; float wv6[6];
    #pragma unroll
    for (int r=0;r<4;r++) xp[r] = *(const u64*)&xb[r*128];
    wv6[0]=wb[o];        wv6[1]=wb[128+o];
    wv6[2]=wb[4096+o];   wv6[3]=wb[4096+128+o];
    wv6[4]=wb[8192+o];   wv6[5]=wb[8192+128+o];

    #pragma unroll 5
    for (int dp=0; dp<15; dp++){
      int d2 = (dp+1)*2;
      u64 xn[4]; float wn[6];
      #pragma unroll
      for (int r=0;r<4;r++) xn[r] = *(const u64*)&xb[r*128 + d2];
      wn[0]=wb[d2*128+o];        wn[1]=wb[(d2+1)*128+o];
      wn[2]=wb[4096+d2*128+o];   wn[3]=wb[4096+(d2+1)*128+o];
      wn[4]=wb[8192+d2*128+o];   wn[5]=wb[8192+(d2+1)*128+o];
      qkvc(aq, ak, av, xp, wv6);
      #pragma unroll
      for (int r=0;r<4;r++) xp[r]=xn[r];
      #pragma unroll
      for (int r=0;r<6;r++) wv6[r]=wn[r];
    }
    qkvc(aq, ak, av, xp, wv6);   // dp = 15
    __syncthreads();
  }

  float bqv = bq[o], bkv = bk[o], bvv = bv[o];
  float qv[4], kv[4], vv[4];
  #pragma unroll
  for (int jr=0;jr<4;jr++){
    float a0,a1;
    unpack2(aq[jr],a0,a1); qv[jr] = a0+a1+bqv;
    unpack2(ak[jr],a0,a1); kv[jr] = a0+a1+bkv;
    unpack2(av[jr],a0,a1); vv[jr] = a0+a1+bvv;
  }
  // primes: q' = 1 - sigmoid(z) = 1/(1+exp(z))
  #pragma unroll
  for (int jr=0;jr<4;jr++){
    qv[jr] = 1.f/(1.f+__expf(qv[jr]));
    kv[jr] = 1.f/(1.f+__expf(kv[jr]));
  }

  #pragma unroll
  for (int jr=0;jr<4;jr++) g_V[(s0 + h*4 + jr)*D_ + o] = vv[jr];

  ((float4*)(g_Qt + b*D_*S_ + o*S_ + sl + h*4))[0] =
      make_float4(qv[0],qv[1],qv[2],qv[3]);
  ((float4*)(g_Kt + b*D_*S_ + o*S_ + sl + h*4))[0] =
      make_float4(kv[0],kv[1],kv[2],kv[3]);

  // totV partial for this block
  wtot[h][o] = vv[0]+vv[1]+vv[2]+vv[3];

  // sumK = 128 - sum_d k'
  float red[4] = {kv[0],kv[1],kv[2],kv[3]};
  #pragma unroll
  for (int off=16; off>=1; off>>=1){
    #pragma unroll
    for (int jr=0;jr<4;jr++) red[jr] += __shfl_xor_sync(0xffffffffu, red[jr], off);
  }
  int w = t >> 5;
  if ((t & 31) == 0){
    #pragma unroll
    for (int jr=0;jr<4;jr++) wred[w][jr] = red[jr];
  }
  __syncthreads();
  if (t < 16){
    int r = t, hh = r >> 2, jr = r & 3;
    float tot = wred[hh*4+0][jr]+wred[hh*4+1][jr]+wred[hh*4+2][jr]+wred[hh*4+3][jr];
    g_sumK[s0 + r] = 128.f - tot;
  }
  if (t < 128)
    g_totVp[blockIdx.x*128 + t] = wtot[0][t]+wtot[1][t]+wtot[2][t]+wtot[3][t];
}

// ---------------- K2: fused truth + E' + Z + E'@V ------------------------
// 144 blocks (one wave, 1/SM): lower-triangle 128q x 64k tiles.
__global__ void __launch_bounds__(512,1) k_main(float* __restrict__ outp){
  extern __shared__ float sm[];
  float* Qts = sm;                 // [128 d][128 q] 16384 fl -> reused as Vs
  float* Kts = sm + 16384;         // [128 d][64 k]   8192 fl -> reused as Es
  float* sKs = sm + 24576;         // [64]
  float* Es  = sm + 16384;         // [64 k][pitch 132] 8448 fl
  float* Vs  = sm;                 // [64 k][128 d]     8192 fl
  int bid = blockIdx.x;
  int t = threadIdx.x;
  float* att = outp + B_*S_*D_;

  int b = bid/72, r = bid - b*72;
  int qt = 0;
  while ((qt+1)*(qt+2) <= r) qt++;
  int k0 = (r - qt*(qt+1))*64;
  int q0 = qt*128;
  int tx = t & 15, ty = t >> 4;    // ty 0..31

  const float4* Qg = (const float4*)(g_Qt + b*D_*S_);
  const float4* Kg = (const float4*)(g_Kt + b*D_*S_);
  const float4* Vg = (const float4*)(g_V + b*S_*D_);

  float4* Qts4 = (float4*)Qts;
  float4* Kts4 = (float4*)Kts;

  // stage Q (8 f4/thr) + K (4 f4/thr) + sKs, one sync
  #pragma unroll
  for (int it=0; it<8; it++){
    int i = t + it*512;                     // 4096 f4
    Qts4[i] = Qg[(i>>5)*256 + (q0>>2) + (i&31)];
  }
  #pragma unroll
  for (int it=0; it<4; it++){
    int i = t + it*512;                     // 2048 f4
    Kts4[i] = Kg[(i>>4)*256 + (k0>>2) + (i&15)];
  }
  if (t < 64) sKs[t] = g_sumK[b*S_ + k0 + t];
  __syncthreads();

  // phase 1: acc = sum_d [k' <= q'] * k'  (software-pipelined: prefetch d+1)
  float acc[4][4];
  #pragma unroll
  for (int i=0;i<4;i++)
    #pragma unroll
    for (int j=0;j<4;j++) acc[i][j] = 0.f;

  {
    float4 qa = Qts4[ty];
    float4 kf = Kts4[tx];
    #pragma unroll 4
    for (int d=0; d<127; d++){
      float4 qn = Qts4[(d+1)*32 + ty];
      float4 kn = Kts4[(d+1)*16 + tx];
      p1c(acc, qa, kf);
      qa = qn; kf = kn;
    }
    p1c(acc, qa, kf);            // d = 127
  }

  // phase 2: T, att store, E' = exp(10T)-1, Z partial
  const float inv = 1.f/128.f;
  float e[4][4];
  #pragma unroll
  for (int i=0;i<4;i++){
    int qg = q0 + ty*4 + i;
    float zrow = 0.f;
    float tt[4];
    #pragma unroll
    for (int j=0;j<4;j++){
      int kg = k0 + tx*4 + j;
      float T = (acc[i][j] + sKs[tx*4+j]) * inv;
      bool val = (kg <= qg);
      T = val ? T : 0.f;
      float ee = val ? (__expf(10.f*T) - 1.f) : 0.f;
      tt[j] = T; e[i][j] = ee; zrow += ee;
    }
    ((float4*)(att + (b*S_ + qg)*S_ + k0 + tx*4))[0] =
        make_float4(tt[0],tt[1],tt[2],tt[3]);
    #pragma unroll
    for (int off=8; off>=1; off>>=1)
      zrow += __shfl_xor_sync(0xffffffffu, zrow, off);
    if (tx == 0) atomicAdd(&g_Z[b*S_ + qg], zrow);
  }
  __syncthreads();     // all reads of Qts/Kts/sKs done

  // phase 3: stage E' (pitch 132, f4-aligned) + V tile
  #pragma unroll
  for (int j=0;j<4;j++){
    int kl = tx*4 + j;
    ((float4*)&Es[kl*132 + ty*4])[0] =
        make_float4(e[0][j], e[1][j], e[2][j], e[3][j]);
  }
  float4* Vs4 = (float4*)Vs;
  #pragma unroll
  for (int it=0; it<4; it++){
    int i = t + it*512;                     // 2048 f4
    Vs4[i] = Vg[(k0 + (i>>5))*32 + (i&31)];
  }
  __syncthreads();

  // phase 4: out += E'^T @ V  (software-pipelined: prefetch k+1)
  u64 acc2[4][4];
  #pragma unroll
  for (int i=0;i<4;i++)
    #pragma unroll
    for (int j=0;j<4;j++) acc2[i][j] = 0ull;

  {
    float4 ef = *(const float4*)&Es[ty*4];
    u64 v[4];
    {
      const u64* vr = (const u64*)&Vs[tx*8];
      v[0]=vr[0]; v[1]=vr[1]; v[2]=vr[2]; v[3]=vr[3];
    }
    #pragma unroll 2
    for (int k=0;k<63;k++){
      float4 efn = *(const float4*)&Es[(k+1)*132 + ty*4];
      u64 vn[4];
      const u64* vrn = (const u64*)&Vs[(k+1)*128 + tx*8];
      vn[0]=vrn[0]; vn[1]=vrn[1]; vn[2]=vrn[2]; vn[3]=vrn[3];
      p4c(acc2, ef, v);
      ef = efn;
      v[0]=vn[0]; v[1]=vn[1]; v[2]=vn[2]; v[3]=vn[3];
    }
    p4c(acc2, ef, v);            // k = 63
  }

  #pragma unroll
  for (int i=0;i<4;i++){
    int qg = q0 + ty*4 + i;
    float* op = outp + (b*S_ + qg)*D_ + tx*8;
    float a0,a1,a2,a3,a4,a5,a6,a7;
    unpack2(acc2[i][0],a0,a1);
    unpack2(acc2[i][1],a2,a3);
    unpack2(acc2[i][2],a4,a5);
    unpack2(acc2[i][3],a6,a7);
    atomicAdd((float4*)op,       make_float4(a0,a1,a2,a3));
    atomicAdd((float4*)(op + 4), make_float4(a4,a5,a6,a7));
  }
}

// ---------------- K3: out = (out + totV) / (Z + 1024) --------------------
// 128 blocks x 256 threads; each block: reduce totVp to smem, then 16 rows.
__global__ void __launch_bounds__(256) k_norm(float* __restrict__ outp){
  __shared__ float4 stot[64];              // [b][32 f4 cols]
  int t = threadIdx.x;
  // reduce the 64 per-qkv-block partials (per batch) into stot
  {
    int ft = t >> 2, p = t & 3;            // ft 0..63 target, p part
    int rb = ft >> 5, col = ft & 31;
    const float4* tp = (const float4*)g_totVp;
    float4 a = make_float4(0.f,0.f,0.f,0.f);
    #pragma unroll 4
    for (int j = p*16; j < p*16+16; j++){
      float4 v = tp[(rb*64 + j)*32 + col];
      a.x+=v.x; a.y+=v.y; a.z+=v.z; a.w+=v.w;
    }
    #pragma unroll
    for (int off=1; off<4; off<<=1){
      a.x += __shfl_xor_sync(0xffffffffu, a.x, off);
      a.y += __shfl_xor_sync(0xffffffffu, a.y, off);
      a.z += __shfl_xor_sync(0xffffffffu, a.z, off);
      a.w += __shfl_xor_sync(0xffffffffu, a.w, off);
    }
    if (p == 0) stot[ft] = a;
  }
  __syncthreads();

  int col = t & 31;
  float4* o4 = (float4*)outp;
  #pragma unroll
  for (int rr=0; rr<2; rr++){
    int row = blockIdx.x*16 + (t>>5) + rr*8;   // 0..2047
    float4 v = o4[row*32 + col];
    float4 tv = stot[((row >> 10) << 5) + col];
    float rz = 1.f/(g_Z[row] + 1024.f);
    v.x=(v.x+tv.x)*rz; v.y=(v.y+tv.y)*rz;
    v.z=(v.z+tv.z)*rz; v.w=(v.w+tv.w)*rz;
    o4[row*32 + col] = v;
  }
}

// ---------------- launch ----------------
extern "C" void kernel_launch(void* const* d_in, const int* in_sizes, int n_in,
                              void* d_out, int out_size){
  (void)in_sizes; (void)n_in; (void)out_size;
  const float* x  = (const float*)d_in[0];
  const float* wq = (const float*)d_in[1];
  const float* bq = (const float*)d_in[2];
  const float* wk = (const float*)d_in[3];
  const float* bk = (const float*)d_in[4];
  const float* wv = (const float*)d_in[5];
  const float* bv = (const float*)d_in[6];
  float* out = (float*)d_out;              // (output, attention_truth)

  const int SMQ = (24576 + 2048) * 4;      // 106,496 B
  const int SMM = 24832 * 4;               // 99,328 B (Es tail included)
  cudaFuncSetAttribute(k_qkv,  cudaFuncAttributeMaxDynamicSharedMemorySize, SMQ);
  cudaFuncSetAttribute(k_main, cudaFuncAttributeMaxDynamicSharedMemorySize, SMM);

  k_qkv  <<< 128, 512, SMQ >>>(x, wq, bq, wk, bk, wv, bv, out);
  k_main <<< 144, 512, SMM >>>(out);
  k_norm <<< 128, 256 >>>(out);
}

// round 12
// speedup vs baseline: 1.0416x; 1.0085x over previous
#include <cuda_runtime.h>
#include <cstdint>

#define B_ 2
#define S_ 1024
#define D_ 128

typedef unsigned long long u64;

// ---------------- scratch ----------------
__device__ float g_Qt[B_*D_*S_];     // q' = 1-Q, transposed [b][d][s]
__device__ float g_Kt[B_*D_*S_];     // k' = 1-K, transposed [b][d][s]
__device__ float g_sumK[B_*S_];      // 128 - sum_d k' per row
__device__ float g_V[B_*S_*D_];      // V [b][s][d]
__device__ float g_Z[B_*S_];         // row sums of E' = exp(10T)-1
__device__ float g_totVp[128*128];   // per-qkv-block partial sums of V

__device__ __forceinline__ u64 pack2(float a, float b){
  u64 r; asm("mov.b64 %0, {%1, %2};" : "=l"(r) : "f"(a), "f"(b)); return r;
}
__device__ __forceinline__ void unpack2(u64 v, float& a, float& b){
  asm("mov.b64 {%0, %1}, %2;" : "=f"(a), "=f"(b) : "l"(v));
}
__device__ __forceinline__ u64 fma2(u64 a, u64 b, u64 c){
  u64 d; asm("fma.rn.f32x2 %0, %1, %2, %3;" : "=l"(d) : "l"(a), "l"(b), "l"(c)); return d;
}

// phase-1 compute: 64 (FSET,FFMA) pairs (8q x 8k)
__device__ __forceinline__ void p1c8(float (&acc)[8][8],
    const float4& qa0, const float4& qa1,
    const float4& kf0, const float4& kf1){
  float qq[8] = {qa0.x,qa0.y,qa0.z,qa0.w, qa1.x,qa1.y,qa1.z,qa1.w};
  float kk[8] = {kf0.x,kf0.y,kf0.z,kf0.w, kf1.x,kf1.y,kf1.z,kf1.w};
  #pragma unroll
  for (int i=0;i<8;i++)
    #pragma unroll
    for (int j=0;j<8;j++)
      asm("{.reg .f32 m; set.le.f32.f32 m, %1, %2; fma.rn.f32 %0, m, %1, %0;}"
          : "+f"(acc[i][j]) : "f"(kk[j]), "f"(qq[i]));
}

// k_qkv inner compute: 12 fma2 (+3 pack)
__device__ __forceinline__ void qkvc(u64 (&aq)[4], u64 (&ak)[4], u64 (&av)[4],
                                     const u64* xp, const float* wv6){
  u64 wqp = pack2(wv6[0], wv6[1]);
  u64 wkp = pack2(wv6[2], wv6[3]);
  u64 wvp = pack2(wv6[4], wv6[5]);
  #pragma unroll
  for (int r=0;r<4;r++){
    aq[r] = fma2(wqp, xp[r], aq[r]);
    ak[r] = fma2(wkp, xp[r], ak[r]);
    av[r] = fma2(wvp, xp[r], av[r]);
  }
}

// ---------------- K1: QKV (+ zero out/Z + zero att upper + totV partials)
// 128 blocks x 512 threads, 16 seq rows per block. (frozen from R10)
__global__ void __launch_bounds__(512,1) k_qkv(
    const float* __restrict__ x,
    const float* __restrict__ wq, const float* __restrict__ bq,
    const float* __restrict__ wk, const float* __restrict__ bk,
    const float* __restrict__ wv, const float* __restrict__ bv,
    float* __restrict__ outp){
  extern __shared__ float sm[];
  float* ws = sm;                 // [2][3][32][128]  = 24576 floats
  float* xs = sm + 24576;         // [16][128]        = 2048 floats
  __shared__ float wred[16][4];
  __shared__ float wtot[4][128];

  int t = threadIdx.x;
  int o = t & 127;
  int h = t >> 7;
  int s0 = blockIdx.x*16;
  int b  = s0 >> 10;
  int sl = s0 & 1023;

  ((float4*)outp)[blockIdx.x*512 + t] = make_float4(0.f,0.f,0.f,0.f);
  if (t < 16) g_Z[blockIdx.x*16 + t] = 0.f;

  {
    float* att = outp + B_*S_*D_;
    int q0u = sl & ~127;
    int start = q0u + 128;
    if (start < 1024){
      int w4 = (1024 - start) >> 2;
      float4 z4 = make_float4(0.f,0.f,0.f,0.f);
      #pragma unroll
      for (int row=0; row<16; row++){
        if (t < w4)
          ((float4*)(att + (b*S_ + sl + row)*S_ + start))[t] = z4;
      }
    }
  }

  ((float4*)xs)[t] = ((const float4*)(x + s0*D_))[t];

  const float4* wq4 = (const float4*)wq;
  const float4* wk4 = (const float4*)wk;
  const float4* wv4 = (const float4*)wv;
  float4* ws4 = (float4*)ws;

  #pragma unroll
  for (int j=0;j<6;j++){
    int i = t + j*512;
    int m = i >> 10, r = i & 1023;
    const float4* src = (m==0)? wq4 : (m==1)? wk4 : wv4;
    ws4[i] = src[((r>>5))*32 + (r&31)];
  }
  __syncthreads();

  u64 aq[4], ak[4], av[4];
  #pragma unroll
  for (int jr=0;jr<4;jr++){ aq[jr]=0ull; ak[jr]=0ull; av[jr]=0ull; }

  #pragma unroll 1
  for (int c=0; c<4; c++){
    if (c < 3){
      int f = (c+1)&1;
      #pragma unroll
      for (int j=0;j<6;j++){
        int i = t + j*512;
        int m = i >> 10, r = i & 1023;
        const float4* src = (m==0)? wq4 : (m==1)? wk4 : wv4;
        ws4[f*3072 + i] = src[((c+1)*32 + (r>>5))*32 + (r&31)];
      }
    }
    const float* wb = ws + (c&1)*12288;
    const float* xb = xs + (h*4)*128 + c*32;

    u64 xp[4]; float wv6[6];
    #pragma unroll
    for (int r=0;r<4;r++) xp[r] = *(const u64*)&xb[r*128];
    wv6[0]=wb[o];        wv6[1]=wb[128+o];
    wv6[2]=wb[4096+o];   wv6[3]=wb[4096+128+o];
    wv6[4]=wb[8192+o];   wv6[5]=wb[8192+128+o];

    #pragma unroll 5
    for (int dp=0; dp<15; dp++){
      int d2 = (dp+1)*2;
      u64 xn[4]; float wn[6];
      #pragma unroll
      for (int r=0;r<4;r++) xn[r] = *(const u64*)&xb[r*128 + d2];
      wn[0]=wb[d2*128+o];        wn[1]=wb[(d2+1)*128+o];
      wn[2]=wb[4096+d2*128+o];   wn[3]=wb[4096+(d2+1)*128+o];
      wn[4]=wb[8192+d2*128+o];   wn[5]=wb[8192+(d2+1)*128+o];
      qkvc(aq, ak, av, xp, wv6);
      #pragma unroll
      for (int r=0;r<4;r++) xp[r]=xn[r];
      #pragma unroll
      for (int r=0;r<6;r++) wv6[r]=wn[r];
    }
    qkvc(aq, ak, av, xp, wv6);
    __syncthreads();
  }

  float bqv = bq[o], bkv = bk[o], bvv = bv[o];
  float qv[4], kv[4], vv[4];
  #pragma unroll
  for (int jr=0;jr<4;jr++){
    float a0,a1;
    unpack2(aq[jr],a0,a1); qv[jr] = a0+a1+bqv;
    unpack2(ak[jr],a0,a1); kv[jr] = a0+a1+bkv;
    unpack2(av[jr],a0,a1); vv[jr] = a0+a1+bvv;
  }
  #pragma unroll
  for (int jr=0;jr<4;jr++){
    qv[jr] = 1.f/(1.f+__expf(qv[jr]));
    kv[jr] = 1.f/(1.f+__expf(kv[jr]));
  }

  #pragma unroll
  for (int jr=0;jr<4;jr++) g_V[(s0 + h*4 + jr)*D_ + o] = vv[jr];

  ((float4*)(g_Qt + b*D_*S_ + o*S_ + sl + h*4))[0] =
      make_float4(qv[0],qv[1],qv[2],qv[3]);
  ((float4*)(g_Kt + b*D_*S_ + o*S_ + sl + h*4))[0] =
      make_float4(kv[0],kv[1],kv[2],kv[3]);

  wtot[h][o] = vv[0]+vv[1]+vv[2]+vv[3];

  float red[4] = {kv[0],kv[1],kv[2],kv[3]};
  #pragma unroll
  for (int off=16; off>=1; off>>=1){
    #pragma unroll
    for (int jr=0;jr<4;jr++) red[jr] += __shfl_xor_sync(0xffffffffu, red[jr], off);
  }
  int w = t >> 5;
  if ((t & 31) == 0){
    #pragma unroll
    for (int jr=0;jr<4;jr++) wred[w][jr] = red[jr];
  }
  __syncthreads();
  if (t < 16){
    int r = t, hh = r >> 2, jr = r & 3;
    float tot = wred[hh*4+0][jr]+wred[hh*4+1][jr]+wred[hh*4+2][jr]+wred[hh*4+3][jr];
    g_sumK[s0 + r] = 128.f - tot;
  }
  if (t < 128)
    g_totVp[blockIdx.x*128 + t] = wtot[0][t]+wtot[1][t]+wtot[2][t]+wtot[3][t];
}

// ---------------- K2: fused truth + E' + Z + E'@V ------------------------
// 144 blocks x 128 threads (4 warps, 1/SMSP): 128q x 64k tiles.
// Fat threads: 8q x 8k in phase 1 (ILP-saturated scalar pipes, minimal LDS).
__global__ void __launch_bounds__(128,1) k_main(float* __restrict__ outp){
  extern __shared__ float sm[];
  float* Qts = sm;                 // [128 d][128 q] 16384 fl -> reused as Vs
  float* Kts = sm + 16384;         // [128 d][64 k]   8192 fl -> reused as Es
  float* sKs = sm + 24576;         // [64]
  float* Es  = sm + 16384;         // [64 k][pitch 132] 8448 fl
  float* Vs  = sm;                 // [64 k][128 d]     8192 fl
  int bid = blockIdx.x;
  int t = threadIdx.x;
  float* att = outp + B_*S_*D_;

  int b = bid/72, r = bid - b*72;
  int qt = 0;
  while ((qt+1)*(qt+2) <= r) qt++;
  int k0 = (r - qt*(qt+1))*64;
  int q0 = qt*128;
  int tx = t & 7, ty = t >> 3;     // ty 0..15 (8 q each), tx 0..7 (8 k each)

  const float4* Qg = (const float4*)(g_Qt + b*D_*S_);
  const float4* Kg = (const float4*)(g_Kt + b*D_*S_);
  const float4* Vg = (const float4*)(g_V + b*S_*D_);

  float4* Qts4 = (float4*)Qts;
  float4* Kts4 = (float4*)Kts;

  // stage Q (32 f4/thr) + K (16 f4/thr) + sKs
  #pragma unroll
  for (int it=0; it<32; it++){
    int i = t + it*128;                     // 4096 f4
    Qts4[i] = Qg[(i>>5)*256 + (q0>>2) + (i&31)];
  }
  #pragma unroll
  for (int it=0; it<16; it++){
    int i = t + it*128;                     // 2048 f4
    Kts4[i] = Kg[(i>>4)*256 + (k0>>2) + (i&15)];
  }
  if (t < 64) sKs[t] = g_sumK[b*S_ + k0 + t];
  __syncthreads();

  // phase 1: acc = sum_d [k' <= q'] * k'   (8q x 8k, prefetch d+1)
  float acc[8][8];
  #pragma unroll
  for (int i=0;i<8;i++)
    #pragma unroll
    for (int j=0;j<8;j++) acc[i][j] = 0.f;

  {
    float4 qa0 = Qts4[ty*2],      qa1 = Qts4[ty*2+1];
    float4 kf0 = Kts4[tx*2],      kf1 = Kts4[tx*2+1];
    #pragma unroll 2
    for (int d=0; d<127; d++){
      float4 qn0 = Qts4[(d+1)*32 + ty*2];
      float4 qn1 = Qts4[(d+1)*32 + ty*2 + 1];
      float4 kn0 = Kts4[(d+1)*16 + tx*2];
      float4 kn1 = Kts4[(d+1)*16 + tx*2 + 1];
      p1c8(acc, qa0, qa1, kf0, kf1);
      qa0=qn0; qa1=qn1; kf0=kn0; kf1=kn1;
    }
    p1c8(acc, qa0, qa1, kf0, kf1);          // d = 127
  }

  // phase 2: T, att store, E' = exp(10T)-1 (overwrites acc), Z partial
  const float inv = 1.f/128.f;
  float sk[8];
  {
    float4 s0v = ((const float4*)&sKs[tx*8])[0];
    float4 s1v = ((const float4*)&sKs[tx*8])[1];
    sk[0]=s0v.x; sk[1]=s0v.y; sk[2]=s0v.z; sk[3]=s0v.w;
    sk[4]=s1v.x; sk[5]=s1v.y; sk[6]=s1v.z; sk[7]=s1v.w;
  }
  #pragma unroll
  for (int i=0;i<8;i++){
    int qg = q0 + ty*8 + i;
    float zrow = 0.f;
    float tt[8];
    #pragma unroll
    for (int j=0;j<8;j++){
      int kg = k0 + tx*8 + j;
      float T = (acc[i][j] + sk[j]) * inv;
      bool val = (kg <= qg);
      T = val ? T : 0.f;
      float ee = val ? (__expf(10.f*T) - 1.f) : 0.f;
      tt[j] = T; acc[i][j] = ee; zrow += ee;
    }
    float* ap = att + (b*S_ + qg)*S_ + k0 + tx*8;
    ((float4*)ap)[0] = make_float4(tt[0],tt[1],tt[2],tt[3]);
    ((float4*)ap)[1] = make_float4(tt[4],tt[5],tt[6],tt[7]);
    #pragma unroll
    for (int off=4; off>=1; off>>=1)
      zrow += __shfl_xor_sync(0xffffffffu, zrow, off);
    if (tx == 0) atomicAdd(&g_Z[b*S_ + qg], zrow);
  }
  __syncthreads();     // all reads of Qts/Kts/sKs done

  // phase 3: stage E' (k-major, pitch 132, tx-rotated store order) + V tile
  #pragma unroll
  for (int jj=0;jj<8;jj++){
    int j = (jj + tx) & 7;                  // rotation kills bank conflicts
    int kl = tx*8 + j;
    float* ep = Es + kl*132 + ty*8;
    ((float4*)ep)[0] = make_float4(acc[0][j],acc[1][j],acc[2][j],acc[3][j]);
    ((float4*)ep)[1] = make_float4(acc[4][j],acc[5][j],acc[6][j],acc[7][j]);
  }
  float4* Vs4 = (float4*)Vs;
  #pragma unroll
  for (int it=0; it<16; it++){
    int i = t + it*128;                     // 2048 f4
    Vs4[i] = Vg[(k0 + (i>>5))*32 + (i&31)];
  }
  __syncthreads();

  // phase 4: out += E'^T @ V   (8q x 32d per thread, f32x2)
  u64 acc2[8][8];
  #pragma unroll
  for (int i=0;i<8;i++)
    #pragma unroll
    for (int j=0;j<8;j++) acc2[i][j] = 0ull;

  #pragma unroll 2
  for (int k=0;k<64;k++){
    float4 e0 = ((const float4*)&Es[k*132 + ty*8])[0];
    float4 e1 = ((const float4*)&Es[k*132 + ty*8])[1];
    float ev[8] = {e0.x,e0.y,e0.z,e0.w, e1.x,e1.y,e1.z,e1.w};
    u64 v[8];
    #pragma unroll
    for (int c=0;c<4;c++){
      float4 vv4 = Vs4[k*32 + tx + 8*c];    // conflict-free (8 consecutive f4)
      v[2*c]   = pack2(vv4.x, vv4.y);
      v[2*c+1] = pack2(vv4.z, vv4.w);
    }
    #pragma unroll
    for (int i=0;i<8;i++){
      u64 e2 = pack2(ev[i], ev[i]);
      #pragma unroll
      for (int j=0;j<8;j++)
        acc2[i][j] = fma2(e2, v[j], acc2[i][j]);
    }
  }

  #pragma unroll
  for (int i=0;i<8;i++){
    int qg = q0 + ty*8 + i;
    float* op = outp + (b*S_ + qg)*D_;
    #pragma unroll
    for (int c=0;c<4;c++){
      float a0,a1,a2,a3;
      unpack2(acc2[i][2*c],   a0,a1);
      unpack2(acc2[i][2*c+1], a2,a3);
      atomicAdd((float4*)(op + (tx + 8*c)*4), make_float4(a0,a1,a2,a3));
    }
  }
}

// ---------------- K3: out = (out + totV) / (Z + 1024) --------------------
__global__ void __launch_bounds__(256) k_norm(float* __restrict__ outp){
  __shared__ float4 stot[64];
  int t = threadIdx.x;
  {
    int ft = t >> 2, p = t & 3;
    int rb = ft >> 5, col = ft & 31;
    const float4* tp = (const float4*)g_totVp;
    float4 a = make_float4(0.f,0.f,0.f,0.f);
    #pragma unroll 4
    for (int j = p*16; j < p*16+16; j++){
      float4 v = tp[(rb*64 + j)*32 + col];
      a.x+=v.x; a.y+=v.y; a.z+=v.z; a.w+=v.w;
    }
    #pragma unroll
    for (int off=1; off<4; off<<=1){
      a.x += __shfl_xor_sync(0xffffffffu, a.x, off);
      a.y += __shfl_xor_sync(0xffffffffu, a.y, off);
      a.z += __shfl_xor_sync(0xffffffffu, a.z, off);
      a.w += __shfl_xor_sync(0xffffffffu, a.w, off);
    }
    if (p == 0) stot[ft] = a;
  }
  __syncthreads();

  int col = t & 31;
  float4* o4 = (float4*)outp;
  #pragma unroll
  for (int rr=0; rr<2; rr++){
    int row = blockIdx.x*16 + (t>>5) + rr*8;
    float4 v = o4[row*32 + col];
    float4 tv = stot[((row >> 10) << 5) + col];
    float rz = 1.f/(g_Z[row] + 1024.f);
    v.x=(v.x+tv.x)*rz; v.y=(v.y+tv.y)*rz;
    v.z=(v.z+tv.z)*rz; v.w=(v.w+tv.w)*rz;
    o4[row*32 + col] = v;
  }
}

// ---------------- launch ----------------
extern "C" void kernel_launch(void* const* d_in, const int* in_sizes, int n_in,
                              void* d_out, int out_size){
  (void)in_sizes; (void)n_in; (void)out_size;
  const float* x  = (const float*)d_in[0];
  const float* wq = (const float*)d_in[1];
  const float* bq = (const float*)d_in[2];
  const float* wk = (const float*)d_in[3];
  const float* bk = (const float*)d_in[4];
  const float* wv = (const float*)d_in[5];
  const float* bv = (const float*)d_in[6];
  float* out = (float*)d_out;              // (output, attention_truth)

  const int SMQ = (24576 + 2048) * 4;      // 106,496 B
  const int SMM = 24832 * 4;               // 99,328 B
  cudaFuncSetAttribute(k_qkv,  cudaFuncAttributeMaxDynamicSharedMemorySize, SMQ);
  cudaFuncSetAttribute(k_main, cudaFuncAttributeMaxDynamicSharedMemorySize, SMM);

  k_qkv  <<< 128, 512, SMQ >>>(x, wq, bq, wk, bk, wv, bv, out);
  k_main <<< 144, 128, SMM >>>(out);
  k_norm <<< 128, 256 >>>(out);
}

// round 13
// speedup vs baseline: 1.0876x; 1.0442x over previous
#include <cuda_runtime.h>
#include <cstdint>

#define B_ 2
#define S_ 1024
#define D_ 128

typedef unsigned long long u64;

// ---------------- scratch ----------------
__device__ float g_Qt[B_*D_*S_];     // q' = 1-Q, transposed [b][d][s]
__device__ float g_Kt[B_*D_*S_];     // k' = 1-K, transposed [b][d][s]
__device__ float g_sumK[B_*S_];      // 128 - sum_d k' per row
__device__ float g_V[B_*S_*D_];      // V [b][s][d]
__device__ float g_Z[B_*S_];         // row sums of E' = exp(10T)-1
__device__ float g_totVp[128*128];   // per-qkv-block partial sums of V

__device__ __forceinline__ u64 pack2(float a, float b){
  u64 r; asm("mov.b64 %0, {%1, %2};" : "=l"(r) : "f"(a), "f"(b)); return r;
}
__device__ __forceinline__ void unpack2(u64 v, float& a, float& b){
  asm("mov.b64 {%0, %1}, %2;" : "=f"(a), "=f"(b) : "l"(v));
}
__device__ __forceinline__ u64 fma2(u64 a, u64 b, u64 c){
  u64 d; asm("fma.rn.f32x2 %0, %1, %2, %3;" : "=l"(d) : "l"(a), "l"(b), "l"(c)); return d;
}
__device__ __forceinline__ unsigned su32(const void* p){
  return (unsigned)__cvta_generic_to_shared(p);
}
#define CP16(s,g) asm volatile("cp.async.cg.shared.global [%0], [%1], 16;" :: "r"(s), "l"(g) : "memory")
#define CPC()  asm volatile("cp.async.commit_group;" ::: "memory")
#define CPW0() asm volatile("cp.async.wait_group 0;" ::: "memory")

// phase-1 compute: 64 (FSET,FFMA) pairs (8q x 8k)
__device__ __forceinline__ void p1c8(float (&acc)[8][8],
    const float4& qa0, const float4& qa1,
    const float4& kf0, const float4& kf1){
  float qq[8] = {qa0.x,qa0.y,qa0.z,qa0.w, qa1.x,qa1.y,qa1.z,qa1.w};
  float kk[8] = {kf0.x,kf0.y,kf0.z,kf0.w, kf1.x,kf1.y,kf1.z,kf1.w};
  #pragma unroll
  for (int i=0;i<8;i++)
    #pragma unroll
    for (int j=0;j<8;j++)
      asm("{.reg .f32 m; set.le.f32.f32 m, %1, %2; fma.rn.f32 %0, m, %1, %0;}"
          : "+f"(acc[i][j]) : "f"(kk[j]), "f"(qq[i]));
}

// k_qkv inner compute: 12 fma2 (+3 pack)
__device__ __forceinline__ void qkvc(u64 (&aq)[4], u64 (&ak)[4], u64 (&av)[4],
                                     const u64* xp, const float* wv6){
  u64 wqp = pack2(wv6[0], wv6[1]);
  u64 wkp = pack2(wv6[2], wv6[3]);
  u64 wvp = pack2(wv6[4], wv6[5]);
  #pragma unroll
  for (int r=0;r<4;r++){
    aq[r] = fma2(wqp, xp[r], aq[r]);
    ak[r] = fma2(wkp, xp[r], ak[r]);
    av[r] = fma2(wvp, xp[r], av[r]);
  }
}

// ---------------- K1: QKV (+ zero out/Z + zero att upper + totV partials)
// 128 blocks x 512 threads, 16 seq rows per block. cp.async staging.
__global__ void __launch_bounds__(512,1) k_qkv(
    const float* __restrict__ x,
    const float* __restrict__ wq, const float* __restrict__ bq,
    const float* __restrict__ wk, const float* __restrict__ bk,
    const float* __restrict__ wv, const float* __restrict__ bv,
    float* __restrict__ outp){
  extern __shared__ float sm[];
  float* ws = sm;                 // [2][3][32][128]  = 24576 floats
  float* xs = sm + 24576;         // [16][128]        = 2048 floats
  __shared__ float wred[16][4];
  __shared__ float wtot[4][128];

  int t = threadIdx.x;
  int o = t & 127;
  int h = t >> 7;
  int s0 = blockIdx.x*16;
  int b  = s0 >> 10;
  int sl = s0 & 1023;

  const float4* wq4 = (const float4*)wq;
  const float4* wk4 = (const float4*)wk;
  const float4* wv4 = (const float4*)wv;
  float4* ws4 = (float4*)ws;
  float4* xs4 = (float4*)xs;

  // stage x tile + weight chunk 0 via cp.async (no register round-trip)
  CP16(su32(&xs4[t]), &((const float4*)(x + s0*D_))[t]);
  #pragma unroll
  for (int j=0;j<6;j++){
    int i = t + j*512;
    int m = i >> 10, r = i & 1023;
    const float4* src = (m==0)? wq4 : (m==1)? wk4 : wv4;
    CP16(su32(&ws4[i]), &src[(r>>5)*32 + (r&31)]);
  }
  CPC();

  // overlap: zero out region + g_Z + att upper triangle while staging lands
  ((float4*)outp)[blockIdx.x*512 + t] = make_float4(0.f,0.f,0.f,0.f);
  if (t < 16) g_Z[blockIdx.x*16 + t] = 0.f;
  {
    float* att = outp + B_*S_*D_;
    int q0u = sl & ~127;
    int start = q0u + 128;
    if (start < 1024){
      int w4 = (1024 - start) >> 2;
      float4 z4 = make_float4(0.f,0.f,0.f,0.f);
      #pragma unroll
      for (int row=0; row<16; row++){
        if (t < w4)
          ((float4*)(att + (b*S_ + sl + row)*S_ + start))[t] = z4;
      }
    }
  }

  CPW0();
  __syncthreads();

  u64 aq[4], ak[4], av[4];
  #pragma unroll
  for (int jr=0;jr<4;jr++){ aq[jr]=0ull; ak[jr]=0ull; av[jr]=0ull; }

  #pragma unroll 1
  for (int c=0; c<4; c++){
    if (c < 3){
      int f = (c+1)&1;
      #pragma unroll
      for (int j=0;j<6;j++){
        int i = t + j*512;
        int m = i >> 10, r = i & 1023;
        const float4* src = (m==0)? wq4 : (m==1)? wk4 : wv4;
        CP16(su32(&ws4[f*3072 + i]), &src[((c+1)*32 + (r>>5))*32 + (r&31)]);
      }
      CPC();
    }
    const float* wb = ws + (c&1)*12288;
    const float* xb = xs + (h*4)*128 + c*32;

    u64 xp[4]; float wv6[6];
    #pragma unroll
    for (int r=0;r<4;r++) xp[r] = *(const u64*)&xb[r*128];
    wv6[0]=wb[o];        wv6[1]=wb[128+o];
    wv6[2]=wb[4096+o];   wv6[3]=wb[4096+128+o];
    wv6[4]=wb[8192+o];   wv6[5]=wb[8192+128+o];

    #pragma unroll 5
    for (int dp=0; dp<15; dp++){
      int d2 = (dp+1)*2;
      u64 xn[4]; float wn[6];
      #pragma unroll
      for (int r=0;r<4;r++) xn[r] = *(const u64*)&xb[r*128 + d2];
      wn[0]=wb[d2*128+o];        wn[1]=wb[(d2+1)*128+o];
      wn[2]=wb[4096+d2*128+o];   wn[3]=wb[4096+(d2+1)*128+o];
      wn[4]=wb[8192+d2*128+o];   wn[5]=wb[8192+(d2+1)*128+o];
      qkvc(aq, ak, av, xp, wv6);
      #pragma unroll
      for (int r=0;r<4;r++) xp[r]=xn[r];
      #pragma unroll
      for (int r=0;r<6;r++) wv6[r]=wn[r];
    }
    qkvc(aq, ak, av, xp, wv6);
    if (c < 3) CPW0();         // prefetch landed during compute
    __syncthreads();
  }

  float bqv = bq[o], bkv = bk[o], bvv = bv[o];
  float qv[4], kv[4], vv[4];
  #pragma unroll
  for (int jr=0;jr<4;jr++){
    float a0,a1;
    unpack2(aq[jr],a0,a1); qv[jr] = a0+a1+bqv;
    unpack2(ak[jr],a0,a1); kv[jr] = a0+a1+bkv;
    unpack2(av[jr],a0,a1); vv[jr] = a0+a1+bvv;
  }
  #pragma unroll
  for (int jr=0;jr<4;jr++){
    qv[jr] = 1.f/(1.f+__expf(qv[jr]));
    kv[jr] = 1.f/(1.f+__expf(kv[jr]));
  }

  #pragma unroll
  for (int jr=0;jr<4;jr++) g_V[(s0 + h*4 + jr)*D_ + o] = vv[jr];

  ((float4*)(g_Qt + b*D_*S_ + o*S_ + sl + h*4))[0] =
      make_float4(qv[0],qv[1],qv[2],qv[3]);
  ((float4*)(g_Kt + b*D_*S_ + o*S_ + sl + h*4))[0] =
      make_float4(kv[0],kv[1],kv[2],kv[3]);

  wtot[h][o] = vv[0]+vv[1]+vv[2]+vv[3];

  float red[4] = {kv[0],kv[1],kv[2],kv[3]};
  #pragma unroll
  for (int off=16; off>=1; off>>=1){
    #pragma unroll
    for (int jr=0;jr<4;jr++) red[jr] += __shfl_xor_sync(0xffffffffu, red[jr], off);
  }
  int w = t >> 5;
  if ((t & 31) == 0){
    #pragma unroll
    for (int jr=0;jr<4;jr++) wred[w][jr] = red[jr];
  }
  __syncthreads();
  if (t < 16){
    int r = t, hh = r >> 2, jr = r & 3;
    float tot = wred[hh*4+0][jr]+wred[hh*4+1][jr]+wred[hh*4+2][jr]+wred[hh*4+3][jr];
    g_sumK[s0 + r] = 128.f - tot;
  }
  if (t < 128)
    g_totVp[blockIdx.x*128 + t] = wtot[0][t]+wtot[1][t]+wtot[2][t]+wtot[3][t];
}

// ---------------- K2: fused truth + E' + Z + E'@V ------------------------
// 144 blocks x 128 threads (4 warps, 1/SMSP): 128q x 64k tiles, fat threads.
__global__ void __launch_bounds__(128,1) k_main(float* __restrict__ outp){
  extern __shared__ float sm[];
  float* Qts = sm;                 // [128 d][128 q] 16384 fl -> reused as Vs
  float* Kts = sm + 16384;         // [128 d][64 k]   8192 fl -> reused as Es
  float* sKs = sm + 24576;         // [64]
  float* Es  = sm + 16384;         // [64 k][pitch 132] 8448 fl
  float* Vs  = sm;                 // [64 k][128 d]     8192 fl
  int bid = blockIdx.x;
  int t = threadIdx.x;
  float* att = outp + B_*S_*D_;

  int b = bid/72, r = bid - b*72;
  int qt = 0;
  while ((qt+1)*(qt+2) <= r) qt++;
  int k0 = (r - qt*(qt+1))*64;
  int q0 = qt*128;
  int tx = t & 7, ty = t >> 3;     // ty 0..15 (8 q each), tx 0..7 (8 k each)

  const float4* Qg = (const float4*)(g_Qt + b*D_*S_);
  const float4* Kg = (const float4*)(g_Kt + b*D_*S_);
  const float4* Vg = (const float4*)(g_V + b*S_*D_);

  float4* Qts4 = (float4*)Qts;
  float4* Kts4 = (float4*)Kts;

  // stage Q + K + sKs via cp.async
  #pragma unroll
  for (int it=0; it<32; it++){
    int i = t + it*128;                     // 4096 f4
    CP16(su32(&Qts4[i]), &Qg[(i>>5)*256 + (q0>>2) + (i&31)]);
  }
  #pragma unroll
  for (int it=0; it<16; it++){
    int i = t + it*128;                     // 2048 f4
    CP16(su32(&Kts4[i]), &Kg[(i>>4)*256 + (k0>>2) + (i&15)]);
  }
  if (t < 16)
    CP16(su32(&sKs[t*4]), (const float4*)&g_sumK[b*S_ + k0 + t*4]);
  CPC();
  CPW0();
  __syncthreads();

  // phase 1: acc = sum_d [k' <= q'] * k'   (8q x 8k, prefetch d+1)
  float acc[8][8];
  #pragma unroll
  for (int i=0;i<8;i++)
    #pragma unroll
    for (int j=0;j<8;j++) acc[i][j] = 0.f;

  {
    float4 qa0 = Qts4[ty*2],      qa1 = Qts4[ty*2+1];
    float4 kf0 = Kts4[tx*2],      kf1 = Kts4[tx*2+1];
    #pragma unroll 2
    for (int d=0; d<127; d++){
      float4 qn0 = Qts4[(d+1)*32 + ty*2];
      float4 qn1 = Qts4[(d+1)*32 + ty*2 + 1];
      float4 kn0 = Kts4[(d+1)*16 + tx*2];
      float4 kn1 = Kts4[(d+1)*16 + tx*2 + 1];
      p1c8(acc, qa0, qa1, kf0, kf1);
      qa0=qn0; qa1=qn1; kf0=kn0; kf1=kn1;
    }
    p1c8(acc, qa0, qa1, kf0, kf1);          // d = 127
  }

  // phase 2: T, att store, E' = exp(10T)-1 (overwrites acc), Z partial
  const float inv = 1.f/128.f;
  float sk[8];
  {
    float4 s0v = ((const float4*)&sKs[tx*8])[0];
    float4 s1v = ((const float4*)&sKs[tx*8])[1];
    sk[0]=s0v.x; sk[1]=s0v.y; sk[2]=s0v.z; sk[3]=s0v.w;
    sk[4]=s1v.x; sk[5]=s1v.y; sk[6]=s1v.z; sk[7]=s1v.w;
  }
  #pragma unroll
  for (int i=0;i<8;i++){
    int qg = q0 + ty*8 + i;
    float zrow = 0.f;
    float tt[8];
    #pragma unroll
    for (int j=0;j<8;j++){
      int kg = k0 + tx*8 + j;
      float T = (acc[i][j] + sk[j]) * inv;
      bool val = (kg <= qg);
      T = val ? T : 0.f;
      float ee = val ? (__expf(10.f*T) - 1.f) : 0.f;
      tt[j] = T; acc[i][j] = ee; zrow += ee;
    }
    float* ap = att + (b*S_ + qg)*S_ + k0 + tx*8;
    ((float4*)ap)[0] = make_float4(tt[0],tt[1],tt[2],tt[3]);
    ((float4*)ap)[1] = make_float4(tt[4],tt[5],tt[6],tt[7]);
    #pragma unroll
    for (int off=4; off>=1; off>>=1)
      zrow += __shfl_xor_sync(0xffffffffu, zrow, off);
    if (tx == 0) atomicAdd(&g_Z[b*S_ + qg], zrow);
  }
  __syncthreads();     // all reads of Qts/Kts/sKs done

  // phase 3: V tile via cp.async (latency overlapped with E' staging)
  float4* Vs4 = (float4*)Vs;
  #pragma unroll
  for (int it=0; it<16; it++){
    int i = t + it*128;                     // 2048 f4
    CP16(su32(&Vs4[i]), &Vg[(k0 + (i>>5))*32 + (i&31)]);
  }
  CPC();
  // stage E' (k-major, pitch 132, tx-rotated store order)
  #pragma unroll
  for (int jj=0;jj<8;jj++){
    int j = (jj + tx) & 7;                  // rotation kills bank conflicts
    int kl = tx*8 + j;
    float* ep = Es + kl*132 + ty*8;
    ((float4*)ep)[0] = make_float4(acc[0][j],acc[1][j],acc[2][j],acc[3][j]);
    ((float4*)ep)[1] = make_float4(acc[4][j],acc[5][j],acc[6][j],acc[7][j]);
  }
  CPW0();
  __syncthreads();

  // phase 4: out += E'^T @ V   (8q x 32d per thread, f32x2)
  u64 acc2[8][8];
  #pragma unroll
  for (int i=0;i<8;i++)
    #pragma unroll
    for (int j=0;j<8;j++) acc2[i][j] = 0ull;

  #pragma unroll 2
  for (int k=0;k<64;k++){
    float4 e0 = ((const float4*)&Es[k*132 + ty*8])[0];
    float4 e1 = ((const float4*)&Es[k*132 + ty*8])[1];
    float ev[8] = {e0.x,e0.y,e0.z,e0.w, e1.x,e1.y,e1.z,e1.w};
    u64 v[8];
    #pragma unroll
    for (int c=0;c<4;c++){
      float4 vv4 = Vs4[k*32 + tx + 8*c];    // conflict-free
      v[2*c]   = pack2(vv4.x, vv4.y);
      v[2*c+1] = pack2(vv4.z, vv4.w);
    }
    #pragma unroll
    for (int i=0;i<8;i++){
      u64 e2 = pack2(ev[i], ev[i]);
      #pragma unroll
      for (int j=0;j<8;j++)
        acc2[i][j] = fma2(e2, v[j], acc2[i][j]);
    }
  }

  #pragma unroll
  for (int i=0;i<8;i++){
    int qg = q0 + ty*8 + i;
    float* op = outp + (b*S_ + qg)*D_;
    #pragma unroll
    for (int c=0;c<4;c++){
      float a0,a1,a2,a3;
      unpack2(acc2[i][2*c],   a0,a1);
      unpack2(acc2[i][2*c+1], a2,a3);
      atomicAdd((float4*)(op + (tx + 8*c)*4), make_float4(a0,a1,a2,a3));
    }
  }
}

// ---------------- K3: out = (out + totV) / (Z + 1024) --------------------
__global__ void __launch_bounds__(256) k_norm(float* __restrict__ outp){
  __shared__ float4 stot[64];
  int t = threadIdx.x;
  {
    int ft = t >> 2, p = t & 3;
    int rb = ft >> 5, col = ft & 31;
    const float4* tp = (const float4*)g_totVp;
    float4 a = make_float4(0.f,0.f,0.f,0.f);
    #pragma unroll 4
    for (int j = p*16; j < p*16+16; j++){
      float4 v = tp[(rb*64 + j)*32 + col];
      a.x+=v.x; a.y+=v.y; a.z+=v.z; a.w+=v.w;
    }
    #pragma unroll
    for (int off=1; off<4; off<<=1){
      a.x += __shfl_xor_sync(0xffffffffu, a.x, off);
      a.y += __shfl_xor_sync(0xffffffffu, a.y, off);
      a.z += __shfl_xor_sync(0xffffffffu, a.z, off);
      a.w += __shfl_xor_sync(0xffffffffu, a.w, off);
    }
    if (p == 0) stot[ft] = a;
  }
  __syncthreads();

  int col = t & 31;
  float4* o4 = (float4*)outp;
  #pragma unroll
  for (int rr=0; rr<2; rr++){
    int row = blockIdx.x*16 + (t>>5) + rr*8;
    float4 v = o4[row*32 + col];
    float4 tv = stot[((row >> 10) << 5) + col];
    float rz = 1.f/(g_Z[row] + 1024.f);
    v.x=(v.x+tv.x)*rz; v.y=(v.y+tv.y)*rz;
    v.z=(v.z+tv.z)*rz; v.w=(v.w+tv.w)*rz;
    o4[row*32 + col] = v;
  }
}

// ---------------- launch ----------------
extern "C" void kernel_launch(void* const* d_in, const int* in_sizes, int n_in,
                              void* d_out, int out_size){
  (void)in_sizes; (void)n_in; (void)out_size;
  const float* x  = (const float*)d_in[0];
  const float* wq = (const float*)d_in[1];
  const float* bq = (const float*)d_in[2];
  const float* wk = (const float*)d_in[3];
  const float* bk = (const float*)d_in[4];
  const float* wv = (const float*)d_in[5];
  const float* bv = (const float*)d_in[6];
  float* out = (float*)d_out;              // (output, attention_truth)

  const int SMQ = (24576 + 2048) * 4;      // 106,496 B
  const int SMM = 24832 * 4;               // 99,328 B
  cudaFuncSetAttribute(k_qkv,  cudaFuncAttributeMaxDynamicSharedMemorySize, SMQ);
  cudaFuncSetAttribute(k_main, cudaFuncAttributeMaxDynamicSharedMemorySize, SMM);

  k_qkv  <<< 128, 512, SMQ >>>(x, wq, bq, wk, bk, wv, bv, out);
  k_main <<< 144, 128, SMM >>>(out);
  k_norm <<< 128, 256 >>>(out);
}